// round 12
// baseline (speedup 1.0000x reference)
#include <cuda_runtime.h>
#include <cooperative_groups.h>

namespace cg = cooperative_groups;

// Problem constants (fixed by the reference)
#define BATCH 128
#define TSTEPS 2048
#define INDIM 32
#define HDIM 256
#define LDIM 16

#define CLS 8          // cluster size = CTAs per batch-group
#define TB 256         // threads per CTA (8 warps; 2 chains x 4 warps)

struct Smem {
    float hbuf[2][2][8][4][32];   // [chain][buf][src rank][batch][lane]  16KB
    float4 scratch[2][4][4][32];  // [chain][kchunk][batch][col]          16KB
    float xbuf[2][2][4][32];      // [chain][buf][batch][dim]              2KB
    unsigned long long mbars[4];  // [chain*2 + buf]
};
#define SMEM_BYTES ((int)sizeof(Smem))

__device__ __forceinline__ unsigned long long pk2(float lo, float hi) {
    return ((unsigned long long)__float_as_uint(hi) << 32) |
           (unsigned long long)__float_as_uint(lo);
}
__device__ __forceinline__ float sum2(unsigned long long v) {
    return __uint_as_float((unsigned int)v) +
           __uint_as_float((unsigned int)(v >> 32));
}
#define FMA2(acc, w, h) \
    asm("fma.rn.f32x2 %0, %1, %2, %0;" : "+l"(acc) : "l"(w), "l"(h))

__device__ __forceinline__ unsigned smem_u32(const void* p) {
    unsigned r;
    asm("{ .reg .u64 t; cvta.to.shared.u64 t, %1; cvt.u32.u64 %0, t; }"
        : "=r"(r) : "l"(p));
    return r;
}

__device__ __forceinline__ float fast_sigmoid(float x) {
    return __fdividef(1.0f, 1.0f + __expf(-x));
}
__device__ __forceinline__ float fast_tanh(float x) {
    float ex = __expf(2.0f * x);
    return fmaf(-2.0f, __fdividef(1.0f, ex + 1.0f), 1.0f);
}

__device__ __forceinline__ void mbar_wait(unsigned addr, unsigned parity) {
    asm volatile(
        "{\n\t"
        ".reg .pred P;\n\t"
        "WL_%=:\n\t"
        "mbarrier.try_wait.parity.acquire.cta.shared::cta.b64 P, [%0], %1, 0x989680;\n\t"
        "@P bra.uni WD_%=;\n\t"
        "bra.uni WL_%=;\n\t"
        "WD_%=:\n\t"
        "}"
        :: "r"(addr), "r"(parity) : "memory");
}
#define CHAIN_BAR(id) \
    asm volatile("bar.sync %0, 128;" :: "r"(id) : "memory")

__global__ void __cluster_dims__(CLS, 1, 1) __launch_bounds__(TB, 1)
gru_persistent_kernel(const float* __restrict__ xg,      // [B,T,IN]
                      const float* __restrict__ xl,      // [B,T,L]
                      const float* __restrict__ h0,      // [B,H]
                      const float* __restrict__ Wih,     // [3H,IN]
                      const float* __restrict__ Whh,     // [3H,H]
                      const float* __restrict__ bias,    // [3H]
                      const float* __restrict__ bias_n,  // [H]
                      float* __restrict__ out)           // [B,T,1]
{
    extern __shared__ __align__(16) char dynsmem[];
    Smem& sm = *reinterpret_cast<Smem*>(dynsmem);

    cg::cluster_group cluster = cg::this_cluster();
    const int rank = (int)cluster.block_rank();     // owns cols [32r, 32r+32)
    const int cid  = blockIdx.x / CLS;              // owns batches [8c, 8c+8)
    const int B0   = cid * 8;
    const int tid  = threadIdx.x;
    const int lane = tid & 31;
    const int warp = tid >> 5;
    const int ch   = warp >> 2;     // chain: 0 = batches 0-3, 1 = batches 4-7
    const int wic  = warp & 3;      // FMA: 64-k chunk; gates: batch-in-chain
    const int col  = rank * 32 + lane;
    const int batch = B0 + ch * 4 + wic;            // this warp's gate-phase batch
    const int barid = 1 + ch;                       // named barrier per chain

    // ---- Weights in registers, packed (even k, odd k) ----
    unsigned long long wd[3][32];   // Whh[g][col][wic*64 .. +63]
    unsigned long long wi[3][4];    // Wih[g][col][wic*8 .. +7]
#pragma unroll
    for (int g = 0; g < 3; g++) {
        const float* wr = Whh + (size_t)(g * HDIM + col) * HDIM + wic * 64;
#pragma unroll
        for (int p = 0; p < 32; p++) wd[g][p] = pk2(wr[2 * p], wr[2 * p + 1]);
        const float* wx = Wih + (size_t)(g * HDIM + col) * INDIM + wic * 8;
#pragma unroll
        for (int q = 0; q < 4; q++) wi[g][q] = pk2(wx[2 * q], wx[2 * q + 1]);
    }
    const float b_r  = bias[col];
    const float b_z  = bias[HDIM + col];
    const float b_ni = bias[2 * HDIM + col];
    const float b_n2 = bias_n[col];

    const unsigned base  = smem_u32(&sm);
    const unsigned hoff  = smem_u32(&sm.hbuf[0][0][0][0][0]) - base;
    const unsigned mboff = smem_u32(&sm.mbars[0]) - base;
    const unsigned mloc  = base + mboff;

    if (tid == 0) {
#pragma unroll
        for (int i = 0; i < 4; i++)
            asm volatile("mbarrier.init.shared.b64 [%0], 1;"
                         :: "r"(mloc + i * 8) : "memory");
    }

    // ---- Init: buf 0 of both chains holds h0, laid out [src][batch][lane] ----
    for (int idx = tid; idx < 2 * 8 * 4 * 32; idx += TB) {
        int c = idx >> 10, src = (idx >> 7) & 7, b = (idx >> 5) & 3, l = idx & 31;
        sm.hbuf[c][0][src][b][l] = h0[(size_t)(B0 + c * 4 + b) * HDIM + src * 32 + l];
    }
    sm.xbuf[ch][0][wic][lane] = xg[(size_t)batch * TSTEPS * INDIM + lane];

    float hreg = h0[(size_t)batch * HDIM + col];    // h_prev (this warp's batch, col)
    float xl_reg = 0.f;
    if (rank == 0 && lane < LDIM)
        xl_reg = xl[(size_t)batch * TSTEPS * LDIM + lane];

    __syncthreads();
    cluster.sync();    // peers' mbarriers initialized before any bulk copy lands

    if (tid == 0) {
#pragma unroll
        for (int c = 0; c < 2; c++) {
            asm volatile("mbarrier.arrive.shared.b64 _, [%0];"
                         :: "r"(mloc + c * 16) : "memory");               // [c][0] done
            asm volatile("mbarrier.arrive.expect_tx.shared.b64 _, [%0], %1;"
                         :: "r"(mloc + c * 16 + 8), "r"(3584u) : "memory"); // arm [c][1]
        }
    }

    // Send targets: chain-lead warp (wic==0), lanes 0..7 -> rank 'lane'
    unsigned peer = 0;
    if (wic == 0 && lane < 8)
        asm("mapa.shared::cluster.u32 %0, %1, %2;" : "=r"(peer) : "r"(base), "r"(lane));

    const unsigned my_mbar0 = mloc + (unsigned)(ch * 16);

    for (int t = 0; t < TSTEPS; t++) {
        const int buf = t & 1;
        const unsigned par = (unsigned)((t >> 1) & 1);
        const int tn = (t + 1 < TSTEPS) ? t + 1 : t;

        mbar_wait(my_mbar0 + (unsigned)(buf * 8), par);   // this chain's h local

        // chain-lead thread re-arms this buffer for step t+2 (bar1 orders it
        // before any of this chain's sends this step; peers transitively later)
        if (wic == 0 && lane == 0 && t + 2 < TSTEPS)
            asm volatile("mbarrier.arrive.expect_tx.shared.b64 _, [%0], %1;"
                         :: "r"(my_mbar0 + (unsigned)(buf * 8)), "r"(3584u) : "memory");

        float xnext = xg[(size_t)batch * TSTEPS * INDIM + (size_t)tn * INDIM + lane];

        // ---- Matvec partials: thread = (col=lane, 64-k chunk = wic) ----
        // 2 groups of 2 batches (limits live accumulators)
#pragma unroll
        for (int bg = 0; bg < 2; bg++) {
            unsigned long long aR[2], aZ[2], aNh[2], aNi[2];
#pragma unroll
            for (int j = 0; j < 2; j++) { aR[j] = 0ull; aZ[j] = 0ull; aNh[j] = 0ull; aNi[j] = 0ull; }

#pragma unroll
            for (int j = 0; j < 2; j++) {
                const int b = bg * 2 + j;
                ulonglong2 x2 = *reinterpret_cast<const ulonglong2*>(
                    &sm.xbuf[ch][buf][b][wic * 8]);
                FMA2(aR[j],  wi[0][0], x2.x); FMA2(aR[j],  wi[0][1], x2.y);
                FMA2(aZ[j],  wi[1][0], x2.x); FMA2(aZ[j],  wi[1][1], x2.y);
                FMA2(aNi[j], wi[2][0], x2.x); FMA2(aNi[j], wi[2][1], x2.y);
                ulonglong2 x3 = *reinterpret_cast<const ulonglong2*>(
                    &sm.xbuf[ch][buf][b][wic * 8 + 4]);
                FMA2(aR[j],  wi[0][2], x3.x); FMA2(aR[j],  wi[0][3], x3.y);
                FMA2(aZ[j],  wi[1][2], x3.x); FMA2(aZ[j],  wi[1][3], x3.y);
                FMA2(aNi[j], wi[2][2], x3.x); FMA2(aNi[j], wi[2][3], x3.y);
            }
            // 64 k's = two source ranks (2*wic, 2*wic+1), 8 x 16B each
#pragma unroll
            for (int half = 0; half < 2; half++) {
#pragma unroll
                for (int i = 0; i < 8; i++) {
#pragma unroll
                    for (int j = 0; j < 2; j++) {
                        const int b = bg * 2 + j;
                        // broadcast LDS.128: all lanes read the same 16B
                        ulonglong2 h2 = *reinterpret_cast<const ulonglong2*>(
                            &sm.hbuf[ch][buf][2 * wic + half][b][4 * i]);
                        const int p = half * 16 + 2 * i;
                        FMA2(aR[j],  wd[0][p],     h2.x);
                        FMA2(aR[j],  wd[0][p + 1], h2.y);
                        FMA2(aZ[j],  wd[1][p],     h2.x);
                        FMA2(aZ[j],  wd[1][p + 1], h2.y);
                        FMA2(aNh[j], wd[2][p],     h2.x);
                        FMA2(aNh[j], wd[2][p + 1], h2.y);
                    }
                }
            }
#pragma unroll
            for (int j = 0; j < 2; j++) {
                sm.scratch[ch][wic][bg * 2 + j][lane] =
                    make_float4(sum2(aR[j]), sum2(aZ[j]), sum2(aNh[j]), sum2(aNi[j]));
            }
        }

        sm.xbuf[ch][buf ^ 1][wic][lane] = xnext;   // pre-bar1; readers post-mbar(t+1)

        CHAIN_BAR(barid);   // bar1: partials + xbuf visible; hbuf reads of t done

        // ---- Reduce + gates: thread = (batch-in-chain = wic, col = lane) ----
        {
            float sR = 0.f, sZ = 0.f, sNh = 0.f, sNi = 0.f;
#pragma unroll
            for (int kc = 0; kc < 4; kc++) {
                float4 v = sm.scratch[ch][kc][wic][lane];
                sR += v.x; sZ += v.y; sNh += v.z; sNi += v.w;
            }
            const float r = fast_sigmoid(sR + b_r);
            const float z = fast_sigmoid(sZ + b_z);
            const float n = fast_tanh(sNi + b_ni + r * (sNh + b_n2));
            hreg = n + z * (hreg - n);
            if (t + 1 < TSTEPS)
                sm.hbuf[ch][buf ^ 1][rank][wic][lane] = hreg;   // stage my row
        }

        CHAIN_BAR(barid);   // bar2: all 4 rows of this chain staged

        // ---- One 512B bulk copy per peer (chain-lead warp, lanes 0..7) ----
        if (t + 1 < TSTEPS && wic == 0 && lane < 8 && lane != rank) {
            asm volatile("fence.proxy.async.shared::cta;" ::: "memory");
            const unsigned off = hoff +
                (unsigned)(((ch * 2 + (buf ^ 1)) * 8 + rank) * 512);
            asm volatile(
                "cp.async.bulk.shared::cluster.shared::cta.mbarrier::complete_tx::bytes "
                "[%0], [%1], %2, [%3];"
                :: "r"(peer + off), "r"(base + off), "r"(512u),
                   "r"(peer + mboff + (unsigned)(ch * 16 + (buf ^ 1) * 8)) : "memory");
        }

        // ---- Readout (columns 0..15 live in rank 0; warp = batch) ----
        if (rank == 0) {
            float prod = (lane < LDIM) ? hreg * xl_reg : 0.f;
#pragma unroll
            for (int o = 16; o; o >>= 1)
                prod += __shfl_xor_sync(0xffffffffu, prod, o);
            if (lane == 0) out[(size_t)batch * TSTEPS + t] = prod;
            if (lane < LDIM)
                xl_reg = xl[(size_t)batch * TSTEPS * LDIM + (size_t)tn * LDIM + lane];
        }
    }

    cluster.sync();   // clean distributed exit
}

extern "C" void kernel_launch(void* const* d_in, const int* in_sizes, int n_in,
                              void* d_out, int out_size) {
    (void)in_sizes; (void)n_in; (void)out_size;
    const float* xg     = (const float*)d_in[0];  // input_gru   [128,2048,32]
    const float* xl     = (const float*)d_in[1];  // input_linear[128,2048,16]
    const float* h0     = (const float*)d_in[2];  // init_hidden [128,256]
    const float* Wih    = (const float*)d_in[3];  // [768,32]
    const float* Whh    = (const float*)d_in[4];  // [768,256]
    const float* bias   = (const float*)d_in[5];  // [768]
    const float* bias_n = (const float*)d_in[6];  // [256]
    float* out = (float*)d_out;                   // [128,2048,1]

    cudaFuncSetAttribute(gru_persistent_kernel,
                         cudaFuncAttributeMaxDynamicSharedMemorySize, SMEM_BYTES);

    gru_persistent_kernel<<<dim3(BATCH), dim3(TB), SMEM_BYTES>>>(
        xg, xl, h0, Wih, Whh, bias, bias_n, out);
}

// round 13
// speedup vs baseline: 1.0184x; 1.0184x over previous
#include <cuda_runtime.h>
#include <cooperative_groups.h>

namespace cg = cooperative_groups;

#define BATCH 128
#define TSTEPS 2048
#define INDIM 32
#define HDIM 256
#define LDIM 16

#define CLS 8          // cluster size = CTAs per batch-group
#define TB 512         // 16 warps = 2 chains x 8 warps

struct Smem {
    float hbuf[2][2][8][4][32];   // [chain][buf][src rank][batch][lane]  16KB
    float4 scratch[2][8][4][32];  // [chain][kchunk][batch][col]          32KB
    float xbuf[2][2][4][32];      // [chain][buf][batch][dim]              2KB
    float4 wsm[8][8][32];         // Nh weights: [kchunk][i][col] = W_n[col][kc*32+4i..+3]  32KB
    unsigned long long mbars[4];  // [chain*2 + buf]
};
#define SMEM_BYTES ((int)sizeof(Smem))

__device__ __forceinline__ unsigned long long pk2(float lo, float hi) {
    return ((unsigned long long)__float_as_uint(hi) << 32) |
           (unsigned long long)__float_as_uint(lo);
}
__device__ __forceinline__ float sum2(unsigned long long v) {
    return __uint_as_float((unsigned int)v) +
           __uint_as_float((unsigned int)(v >> 32));
}
#define FMA2(acc, w, h) \
    asm("fma.rn.f32x2 %0, %1, %2, %0;" : "+l"(acc) : "l"(w), "l"(h))

__device__ __forceinline__ unsigned smem_u32(const void* p) {
    unsigned r;
    asm("{ .reg .u64 t; cvta.to.shared.u64 t, %1; cvt.u32.u64 %0, t; }"
        : "=r"(r) : "l"(p));
    return r;
}
__device__ __forceinline__ float fast_sigmoid(float x) {
    return __fdividef(1.0f, 1.0f + __expf(-x));
}
__device__ __forceinline__ float fast_tanh(float x) {
    float ex = __expf(2.0f * x);
    return fmaf(-2.0f, __fdividef(1.0f, ex + 1.0f), 1.0f);
}
__device__ __forceinline__ void mbar_wait(unsigned addr, unsigned parity) {
    asm volatile(
        "{\n\t"
        ".reg .pred P;\n\t"
        "WL_%=:\n\t"
        "mbarrier.try_wait.parity.acquire.cta.shared::cta.b64 P, [%0], %1, 0x989680;\n\t"
        "@P bra.uni WD_%=;\n\t"
        "bra.uni WL_%=;\n\t"
        "WD_%=:\n\t"
        "}"
        :: "r"(addr), "r"(parity) : "memory");
}
#define CHAIN_BAR(id) asm volatile("bar.sync %0, 256;" :: "r"(id) : "memory")

__global__ void __cluster_dims__(CLS, 1, 1) __launch_bounds__(TB, 1)
gru_persistent_kernel(const float* __restrict__ xg,      // [B,T,IN]
                      const float* __restrict__ xl,      // [B,T,L]
                      const float* __restrict__ h0,      // [B,H]
                      const float* __restrict__ Wih,     // [3H,IN]
                      const float* __restrict__ Whh,     // [3H,H]
                      const float* __restrict__ bias,    // [3H]
                      const float* __restrict__ bias_n,  // [H]
                      float* __restrict__ out)           // [B,T,1]
{
    extern __shared__ __align__(16) char dynsmem[];
    Smem& sm = *reinterpret_cast<Smem*>(dynsmem);

    cg::cluster_group cluster = cg::this_cluster();
    const int rank = (int)cluster.block_rank();     // owns cols [32r, 32r+32)
    const int cid  = blockIdx.x / CLS;              // owns batches [8c, 8c+8)
    const int B0   = cid * 8;
    const int tid  = threadIdx.x;
    const int lane = tid & 31;
    const int warp = tid >> 5;
    const int s    = warp & 3;                      // SMSP
    const int g    = warp >> 2;                     // group 0..3
    const int ch   = g & 1;                         // chain: A=0 (batches 0-3), B=1 (4-7)
    const int cw   = s + ((g >> 1) << 2);           // chain-warp 0..7 = k-chunk / src rank
    const int col  = rank * 32 + lane;
    const int isgate = (cw < 4);
    const int batch  = B0 + ch * 4 + cw;            // valid when isgate
    const int barid  = 1 + ch;

    // ---- R,Z recurrent weights + all x-side weights in registers ----
    unsigned long long wd[2][16];   // Whh[{r,z}][col][cw*32 .. +31]
    unsigned long long wi[3][2];    // Wih[g][col][cw*4 .. +3]
#pragma unroll
    for (int gg = 0; gg < 2; gg++) {
        const float* wr = Whh + (size_t)(gg * HDIM + col) * HDIM + cw * 32;
#pragma unroll
        for (int p = 0; p < 16; p++) wd[gg][p] = pk2(wr[2 * p], wr[2 * p + 1]);
    }
#pragma unroll
    for (int gg = 0; gg < 3; gg++) {
        const float* wx = Wih + (size_t)(gg * HDIM + col) * INDIM + cw * 4;
        wi[gg][0] = pk2(wx[0], wx[1]);
        wi[gg][1] = pk2(wx[2], wx[3]);
    }
    const float b_r  = bias[col];
    const float b_z  = bias[HDIM + col];
    const float b_ni = bias[2 * HDIM + col];
    const float b_n2 = bias_n[col];

    // ---- Nh recurrent weights into SMEM (shared by both chains) ----
    // wsm[kc][i][c] = W_n[rank*32+c][kc*32 + 4i .. +3]
    for (int idx = tid; idx < 8 * 8 * 32; idx += TB) {
        int kc = idx >> 8, i = (idx >> 5) & 7, c = idx & 31;
        const float* wn = Whh + (size_t)(2 * HDIM + rank * 32 + c) * HDIM + kc * 32 + 4 * i;
        sm.wsm[kc][i][c] = make_float4(wn[0], wn[1], wn[2], wn[3]);
    }

    const unsigned base  = smem_u32(&sm);
    const unsigned hoff  = smem_u32(&sm.hbuf[0][0][0][0][0]) - base;
    const unsigned mboff = smem_u32(&sm.mbars[0]) - base;
    const unsigned mloc  = base + mboff;

    if (tid == 0) {
#pragma unroll
        for (int i = 0; i < 4; i++)
            asm volatile("mbarrier.init.shared.b64 [%0], 1;"
                         :: "r"(mloc + i * 8) : "memory");
    }

    // ---- Init: buf 0 of both chains holds h0: [src][batch][lane] ----
    for (int idx = tid; idx < 2 * 8 * 4 * 32; idx += TB) {
        int c = idx >> 10, src = (idx >> 7) & 7, b = (idx >> 5) & 3, l = idx & 31;
        sm.hbuf[c][0][src][b][l] = h0[(size_t)(B0 + c * 4 + b) * HDIM + src * 32 + l];
    }
    float hreg = 0.f, xl_reg = 0.f;
    if (isgate) {
        sm.xbuf[ch][0][cw][lane] = xg[(size_t)batch * TSTEPS * INDIM + lane];
        hreg = h0[(size_t)batch * HDIM + col];
        if (rank == 0 && lane < LDIM)
            xl_reg = xl[(size_t)batch * TSTEPS * LDIM + lane];
    }

    __syncthreads();
    cluster.sync();    // peers' mbarriers + wsm ready before any traffic

    if (tid == 0) {
#pragma unroll
        for (int c = 0; c < 2; c++) {
            asm volatile("mbarrier.arrive.shared.b64 _, [%0];"
                         :: "r"(mloc + c * 16) : "memory");                 // [c][0] done
            asm volatile("mbarrier.arrive.expect_tx.shared.b64 _, [%0], %1;"
                         :: "r"(mloc + c * 16 + 8), "r"(3584u) : "memory"); // arm [c][1]
        }
    }

    unsigned peer = 0;
    if (cw == 0 && lane < 8)   // chain-lead warp sends; lane -> rank
        asm("mapa.shared::cluster.u32 %0, %1, %2;" : "=r"(peer) : "r"(base), "r"(lane));

    const unsigned my_mbar0 = mloc + (unsigned)(ch * 16);

    // ---- anti-phase seed: chain B waits until chain A finishes its first FMA ----
    if (ch == 1)
        asm volatile("bar.sync 3, 512;" ::: "memory");

    for (int t = 0; t < TSTEPS; t++) {
        const int buf = t & 1;
        const unsigned par = (unsigned)((t >> 1) & 1);
        const int tn = (t + 1 < TSTEPS) ? t + 1 : t;

        mbar_wait(my_mbar0 + (unsigned)(buf * 8), par);   // this chain's full h local

        if (cw == 0 && lane == 0 && t + 2 < TSTEPS)       // re-arm for t+2 (pre-bar1)
            asm volatile("mbarrier.arrive.expect_tx.shared.b64 _, [%0], %1;"
                         :: "r"(my_mbar0 + (unsigned)(buf * 8)), "r"(3584u) : "memory");

        float xnext = 0.f;
        if (isgate)
            xnext = xg[(size_t)batch * TSTEPS * INDIM + (size_t)tn * INDIM + lane];

        // ---- Matvec partials: thread = (col=lane, 32-k chunk = cw), 4 batches ----
#pragma unroll
        for (int bg = 0; bg < 2; bg++) {
            unsigned long long aR[2], aZ[2], aNh[2], aNi[2];
#pragma unroll
            for (int j = 0; j < 2; j++) { aR[j] = 0ull; aZ[j] = 0ull; aNh[j] = 0ull; aNi[j] = 0ull; }

#pragma unroll
            for (int j = 0; j < 2; j++) {
                const int b = bg * 2 + j;
                ulonglong2 x2 = *reinterpret_cast<const ulonglong2*>(
                    &sm.xbuf[ch][buf][b][cw * 4]);
                FMA2(aR[j],  wi[0][0], x2.x); FMA2(aR[j],  wi[0][1], x2.y);
                FMA2(aZ[j],  wi[1][0], x2.x); FMA2(aZ[j],  wi[1][1], x2.y);
                FMA2(aNi[j], wi[2][0], x2.x); FMA2(aNi[j], wi[2][1], x2.y);
            }
#pragma unroll
            for (int i = 0; i < 8; i++) {
                // Nh weights for this 16B chunk (per-lane distinct LDS.128)
                ulonglong2 wn = *reinterpret_cast<const ulonglong2*>(&sm.wsm[cw][i][lane]);
#pragma unroll
                for (int j = 0; j < 2; j++) {
                    const int b = bg * 2 + j;
                    // broadcast LDS.128: all lanes read the same 16B of h
                    ulonglong2 h2 = *reinterpret_cast<const ulonglong2*>(
                        &sm.hbuf[ch][buf][cw][b][4 * i]);
                    FMA2(aR[j],  wd[0][2 * i],     h2.x);
                    FMA2(aR[j],  wd[0][2 * i + 1], h2.y);
                    FMA2(aZ[j],  wd[1][2 * i],     h2.x);
                    FMA2(aZ[j],  wd[1][2 * i + 1], h2.y);
                    FMA2(aNh[j], wn.x,             h2.x);
                    FMA2(aNh[j], wn.y,             h2.y);
                }
            }
#pragma unroll
            for (int j = 0; j < 2; j++) {
                sm.scratch[ch][cw][bg * 2 + j][lane] =
                    make_float4(sum2(aR[j]), sum2(aZ[j]), sum2(aNh[j]), sum2(aNi[j]));
            }
        }

        if (isgate) sm.xbuf[ch][buf ^ 1][cw][lane] = xnext;   // pre-bar1

        CHAIN_BAR(barid);   // bar1: partials + xbuf visible; hbuf reads of t done

        if (t == 0 && ch == 0)   // release chain B ~half a step behind
            asm volatile("bar.arrive 3, 512;" ::: "memory");

        // ---- Reduce + gates: thread = (batch-in-chain = cw, col = lane) ----
        if (isgate) {
            float sR = 0.f, sZ = 0.f, sNh = 0.f, sNi = 0.f;
#pragma unroll
            for (int kc = 0; kc < 8; kc++) {
                float4 v = sm.scratch[ch][kc][cw][lane];
                sR += v.x; sZ += v.y; sNh += v.z; sNi += v.w;
            }
            const float r = fast_sigmoid(sR + b_r);
            const float z = fast_sigmoid(sZ + b_z);
            const float n = fast_tanh(sNi + b_ni + r * (sNh + b_n2));
            hreg = n + z * (hreg - n);
            if (t + 1 < TSTEPS)
                sm.hbuf[ch][buf ^ 1][rank][cw][lane] = hreg;   // stage my row
        }

        CHAIN_BAR(barid);   // bar2: all 4 rows of this chain staged

        // ---- One 512B bulk copy per peer (chain-lead warp, lanes 0..7) ----
        if (t + 1 < TSTEPS && cw == 0 && lane < 8 && lane != rank) {
            asm volatile("fence.proxy.async.shared::cta;" ::: "memory");
            const unsigned off = hoff +
                (unsigned)(ch * 8192 + (buf ^ 1) * 4096 + rank * 512);
            asm volatile(
                "cp.async.bulk.shared::cluster.shared::cta.mbarrier::complete_tx::bytes "
                "[%0], [%1], %2, [%3];"
                :: "r"(peer + off), "r"(base + off), "r"(512u),
                   "r"(peer + mboff + (unsigned)(ch * 16 + (buf ^ 1) * 8)) : "memory");
        }

        // ---- Readout (columns 0..15 live in rank 0) ----
        if (rank == 0 && isgate) {
            float prod = (lane < LDIM) ? hreg * xl_reg : 0.f;
#pragma unroll
            for (int o = 16; o; o >>= 1)
                prod += __shfl_xor_sync(0xffffffffu, prod, o);
            if (lane == 0) out[(size_t)batch * TSTEPS + t] = prod;
            if (lane < LDIM)
                xl_reg = xl[(size_t)batch * TSTEPS * LDIM + (size_t)tn * LDIM + lane];
        }
    }

    cluster.sync();   // clean distributed exit
}

extern "C" void kernel_launch(void* const* d_in, const int* in_sizes, int n_in,
                              void* d_out, int out_size) {
    (void)in_sizes; (void)n_in; (void)out_size;
    const float* xg     = (const float*)d_in[0];
    const float* xl     = (const float*)d_in[1];
    const float* h0     = (const float*)d_in[2];
    const float* Wih    = (const float*)d_in[3];
    const float* Whh    = (const float*)d_in[4];
    const float* bias   = (const float*)d_in[5];
    const float* bias_n = (const float*)d_in[6];
    float* out = (float*)d_out;

    cudaFuncSetAttribute(gru_persistent_kernel,
                         cudaFuncAttributeMaxDynamicSharedMemorySize, SMEM_BYTES);

    gru_persistent_kernel<<<dim3(BATCH), dim3(TB), SMEM_BYTES>>>(
        xg, xl, h0, Wih, Whh, bias, bias_n, out);
}

// round 14
// speedup vs baseline: 1.2542x; 1.2315x over previous
#include <cuda_runtime.h>
#include <cooperative_groups.h>

namespace cg = cooperative_groups;

#define BATCH 128
#define TSTEPS 2048
#define INDIM 32
#define HDIM 256
#define LDIM 16

#define CLS 8          // cluster size = CTAs per batch-group
#define TB 256         // threads per CTA (8 warps)

struct Smem {
    float hbuf[2][8][8][32];      // [buf][src rank][batch][lane]  16KB
    float4 scratch[2][8][8][32];  // [parity][kchunk][batch][col]  64KB
    float xbuf[2][8][32];         // [parity][batch][dim]           2KB
    float stage[8][32];           // my CTA's h rows (send source)  1KB
    unsigned long long mbars[16]; // [buf][src rank]
};
#define SMEM_BYTES ((int)sizeof(Smem))

__device__ __forceinline__ unsigned long long pk2(float lo, float hi) {
    return ((unsigned long long)__float_as_uint(hi) << 32) |
           (unsigned long long)__float_as_uint(lo);
}
__device__ __forceinline__ float sum2(unsigned long long v) {
    return __uint_as_float((unsigned int)v) +
           __uint_as_float((unsigned int)(v >> 32));
}
#define FMA2(acc, w, h) \
    asm("fma.rn.f32x2 %0, %1, %2, %0;" : "+l"(acc) : "l"(w), "l"(h))

__device__ __forceinline__ unsigned smem_u32(const void* p) {
    unsigned r;
    asm("{ .reg .u64 t; cvta.to.shared.u64 t, %1; cvt.u32.u64 %0, t; }"
        : "=r"(r) : "l"(p));
    return r;
}
__device__ __forceinline__ float fast_sigmoid(float x) {
    return __fdividef(1.0f, 1.0f + __expf(-x));
}
__device__ __forceinline__ float fast_tanh(float x) {
    float ex = __expf(2.0f * x);
    return fmaf(-2.0f, __fdividef(1.0f, ex + 1.0f), 1.0f);
}
__device__ __forceinline__ void mbar_wait(unsigned addr, unsigned parity) {
    asm volatile(
        "{\n\t"
        ".reg .pred P;\n\t"
        "WL_%=:\n\t"
        "mbarrier.try_wait.parity.acquire.cta.shared::cta.b64 P, [%0], %1, 0x989680;\n\t"
        "@P bra.uni WD_%=;\n\t"
        "bra.uni WL_%=;\n\t"
        "WD_%=:\n\t"
        "}"
        :: "r"(addr), "r"(parity) : "memory");
}

__global__ void __cluster_dims__(CLS, 1, 1) __launch_bounds__(TB, 1)
gru_persistent_kernel(const float* __restrict__ xg,      // [B,T,IN]
                      const float* __restrict__ xl,      // [B,T,L]
                      const float* __restrict__ h0,      // [B,H]
                      const float* __restrict__ Wih,     // [3H,IN]
                      const float* __restrict__ Whh,     // [3H,H]
                      const float* __restrict__ bias,    // [3H]
                      const float* __restrict__ bias_n,  // [H]
                      float* __restrict__ out)           // [B,T,1]
{
    extern __shared__ __align__(16) char dynsmem[];
    Smem& sm = *reinterpret_cast<Smem*>(dynsmem);

    cg::cluster_group cluster = cg::this_cluster();
    const int rank = (int)cluster.block_rank();     // owns cols [32r, 32r+32)
    const int cid  = blockIdx.x / CLS;              // owns batches [8c, 8c+8)
    const int B0   = cid * 8;
    const int tid  = threadIdx.x;
    const int lane = tid & 31;
    const int warp = tid >> 5;      // FMA: consumes src rank 'warp'; gates: batch 'warp'
    const int col  = rank * 32 + lane;

    // ---- Weights in registers, packed (even k, odd k) ----
    unsigned long long wd[3][16];   // Whh[g][col][warp*32 .. +31]
    unsigned long long wi[3][2];    // Wih[g][col][warp*4 .. +3]
#pragma unroll
    for (int g = 0; g < 3; g++) {
        const float* wr = Whh + (size_t)(g * HDIM + col) * HDIM + warp * 32;
#pragma unroll
        for (int p = 0; p < 16; p++) wd[g][p] = pk2(wr[2 * p], wr[2 * p + 1]);
        const float* wx = Wih + (size_t)(g * HDIM + col) * INDIM + warp * 4;
        wi[g][0] = pk2(wx[0], wx[1]);
        wi[g][1] = pk2(wx[2], wx[3]);
    }
    const float b_r  = bias[col];
    const float b_z  = bias[HDIM + col];
    const float b_ni = bias[2 * HDIM + col];
    const float b_n2 = bias_n[col];

    const unsigned base  = smem_u32(&sm);
    const unsigned hoff  = smem_u32(&sm.hbuf[0][0][0][0]) - base;
    const unsigned soff  = smem_u32(&sm.stage[0][0]) - base;
    const unsigned mboff = smem_u32(&sm.mbars[0]) - base;
    const unsigned mloc  = base + mboff;

    if (tid == 0) {
#pragma unroll
        for (int i = 0; i < 16; i++)
            asm volatile("mbarrier.init.shared.b64 [%0], 1;"
                         :: "r"(mloc + i * 8) : "memory");
    }

    // ---- Init: buffer 0 holds full h0, laid out [src][batch][lane] ----
    for (int idx = tid; idx < 8 * HDIM; idx += TB) {
        int src = idx >> 8, b = (idx >> 5) & 7, l = idx & 31;
        sm.hbuf[0][src][b][l] = h0[(size_t)(B0 + b) * HDIM + src * 32 + l];
    }
    sm.xbuf[0][warp][lane] = xg[(size_t)(B0 + warp) * TSTEPS * INDIM + lane];

    float hreg = h0[(size_t)(B0 + warp) * HDIM + col];   // h_prev (batch B0+warp, col)
    float xl_reg = 0.f;
    if (rank == 0 && lane < LDIM)
        xl_reg = xl[(size_t)(B0 + warp) * TSTEPS * LDIM + lane];

    __syncthreads();
    cluster.sync();    // peers' mbarriers initialized before any bulk copy lands

    if (tid == 0) {
#pragma unroll
        for (int s = 0; s < 8; s++) {
            // buf 0 pre-filled locally -> complete phase 0
            asm volatile("mbarrier.arrive.shared.b64 _, [%0];"
                         :: "r"(mloc + s * 8) : "memory");
            // arm buf 1 per-source: 8 rows x 128B from that source
            asm volatile("mbarrier.arrive.expect_tx.shared.b64 _, [%0], %1;"
                         :: "r"(mloc + (8 + s) * 8), "r"(1024u) : "memory");
        }
    }

    // Send targets: every gate warp, lanes 0..7 -> rank 'lane' (incl. self)
    unsigned peer = 0;
    if (lane < 8)
        asm("mapa.shared::cluster.u32 %0, %1, %2;" : "=r"(peer) : "r"(base), "r"(lane));

    for (int t = 0; t < TSTEPS; t++) {
        const int buf = t & 1;
        const unsigned par = (unsigned)((t >> 1) & 1);
        const int tn = (t + 1 < TSTEPS) ? t + 1 : t;
        const unsigned my_mbar = mloc + (unsigned)((buf * 8 + warp) * 8);

        mbar_wait(my_mbar, par);   // only THIS warp's source slice must be local

        // re-arm this source's mbar for t+2 (pre-S1; proof via peer handshake)
        if (lane == 0 && t + 2 < TSTEPS)
            asm volatile("mbarrier.arrive.expect_tx.shared.b64 _, [%0], %1;"
                         :: "r"(my_mbar), "r"(1024u) : "memory");

        float xnext = xg[(size_t)(B0 + warp) * TSTEPS * INDIM +
                         (size_t)tn * INDIM + lane];

        // ---- Matvec partials: thread = (col=lane, src slice = warp) ----
#pragma unroll
        for (int bg = 0; bg < 2; bg++) {
            unsigned long long aR[4], aZ[4], aNh[4], aNi[4];
#pragma unroll
            for (int j = 0; j < 4; j++) { aR[j] = 0ull; aZ[j] = 0ull; aNh[j] = 0ull; aNi[j] = 0ull; }

#pragma unroll
            for (int j = 0; j < 4; j++) {
                const int b = bg * 4 + j;
                ulonglong2 x2 = *reinterpret_cast<const ulonglong2*>(
                    &sm.xbuf[buf][b][warp * 4]);
                FMA2(aR[j],  wi[0][0], x2.x); FMA2(aR[j],  wi[0][1], x2.y);
                FMA2(aZ[j],  wi[1][0], x2.x); FMA2(aZ[j],  wi[1][1], x2.y);
                FMA2(aNi[j], wi[2][0], x2.x); FMA2(aNi[j], wi[2][1], x2.y);
            }
#pragma unroll
            for (int i = 0; i < 8; i++) {
#pragma unroll
                for (int j = 0; j < 4; j++) {
                    const int b = bg * 4 + j;
                    // broadcast LDS.128: all lanes read the same 16B
                    ulonglong2 h2 = *reinterpret_cast<const ulonglong2*>(
                        &sm.hbuf[buf][warp][b][4 * i]);
                    FMA2(aR[j],  wd[0][2 * i],     h2.x);
                    FMA2(aR[j],  wd[0][2 * i + 1], h2.y);
                    FMA2(aZ[j],  wd[1][2 * i],     h2.x);
                    FMA2(aZ[j],  wd[1][2 * i + 1], h2.y);
                    FMA2(aNh[j], wd[2][2 * i],     h2.x);
                    FMA2(aNh[j], wd[2][2 * i + 1], h2.y);
                }
            }
#pragma unroll
            for (int j = 0; j < 4; j++) {
                sm.scratch[buf][warp][bg * 4 + j][lane] =
                    make_float4(sum2(aR[j]), sum2(aZ[j]), sum2(aNh[j]), sum2(aNi[j]));
            }
        }

        sm.xbuf[buf ^ 1][warp][lane] = xnext;   // parity buffer; readers post-S1(t+1)-wait

        __syncthreads();   // S1: sole block barrier — orders everything intra-CTA

        // ---- Reduce + gates: thread = (batch=warp, col=lane) ----
        {
            float sR = 0.f, sZ = 0.f, sNh = 0.f, sNi = 0.f;
#pragma unroll
            for (int kc = 0; kc < 8; kc++) {
                float4 v = sm.scratch[buf][kc][warp][lane];
                sR += v.x; sZ += v.y; sNh += v.z; sNi += v.w;
            }
            const float r = fast_sigmoid(sR + b_r);
            const float z = fast_sigmoid(sZ + b_z);
            const float n = fast_tanh(sNi + b_ni + r * (sNh + b_n2));
            hreg = n + z * (hreg - n);
        }

        // ---- Eager per-warp exchange: stage my 128B row, send to all 8 ranks ----
        if (t + 1 < TSTEPS) {
            sm.stage[warp][lane] = hreg;
            __syncwarp();
            asm volatile("fence.proxy.async.shared::cta;" ::: "memory");
            if (lane < 8) {
                const unsigned src = base + soff + (unsigned)(warp * 128);
                const unsigned dst = peer + hoff +
                    (unsigned)((buf ^ 1) * 8192 + rank * 1024 + warp * 128);
                const unsigned dmb = peer + mboff +
                    (unsigned)(((buf ^ 1) * 8 + rank) * 8);
                asm volatile(
                    "cp.async.bulk.shared::cluster.shared::cta.mbarrier::complete_tx::bytes "
                    "[%0], [%1], %2, [%3];"
                    :: "r"(dst), "r"(src), "r"(128u), "r"(dmb) : "memory");
            }
        }

        // ---- Readout (columns 0..15 live in rank 0) ----
        if (rank == 0) {
            float prod = (lane < LDIM) ? hreg * xl_reg : 0.f;
#pragma unroll
            for (int o = 16; o; o >>= 1)
                prod += __shfl_xor_sync(0xffffffffu, prod, o);
            if (lane == 0) out[(size_t)(B0 + warp) * TSTEPS + t] = prod;
            if (lane < LDIM)
                xl_reg = xl[(size_t)(B0 + warp) * TSTEPS * LDIM +
                            (size_t)tn * LDIM + lane];
        }
    }

    cluster.sync();   // clean distributed exit

    // NOTE: stage[] rows for step t are consumed (bulk-read) before the same
    // warp can overwrite them at t+1, because the overwrite follows S1(t+1)
    // ... actually the overwrite follows gates(t+1) which follows S1(t+1),
    // which follows this warp's wait(t+1); the bulk engine read of stage(t)
    // precedes its mbar completion at peers, which precedes THEIR sends for
    // t+2 — but our own t+1 staging only needs our own engine to have READ
    // stage(t). cp.async.bulk reads source before signaling completion at the
    // destination; our wait(t+1) on mbar[warp] completes only after rank
    // 'warp''s copies (not ours) — however our own t+1 stage write is to the
    // same address our engine read for t: the engine's source read completes
    // before the destination mbar completes; destination (peer) mbar for
    // [buf^1] gates peer's FMA(t+1) -> peer S1(t+1) -> peer sends(t+2) -> our
    // mbar[peer][buf] (t+2). Our stage overwrite at t+1 happens after our
    // S1(t+1), i.e. after ALL our warps' waits(t+1), i.e. after all 8 sources'
    // t+1 copies completed at us — which includes OUR OWN self-copy (lane ==
    // rank) whose completion implies our engine finished reading stage(t).
}

extern "C" void kernel_launch(void* const* d_in, const int* in_sizes, int n_in,
                              void* d_out, int out_size) {
    (void)in_sizes; (void)n_in; (void)out_size;
    const float* xg     = (const float*)d_in[0];  // input_gru   [128,2048,32]
    const float* xl     = (const float*)d_in[1];  // input_linear[128,2048,16]
    const float* h0     = (const float*)d_in[2];  // init_hidden [128,256]
    const float* Wih    = (const float*)d_in[3];  // [768,32]
    const float* Whh    = (const float*)d_in[4];  // [768,256]
    const float* bias   = (const float*)d_in[5];  // [768]
    const float* bias_n = (const float*)d_in[6];  // [256]
    float* out = (float*)d_out;                   // [128,2048,1]

    cudaFuncSetAttribute(gru_persistent_kernel,
                         cudaFuncAttributeMaxDynamicSharedMemorySize, SMEM_BYTES);

    gru_persistent_kernel<<<dim3(BATCH), dim3(TB), SMEM_BYTES>>>(
        xg, xl, h0, Wih, Whh, bias, bias_n, out);
}